// round 4
// baseline (speedup 1.0000x reference)
#include <cuda_runtime.h>

#define NT 544

typedef unsigned long long ull;

// Scratch (allowed: __device__ globals, no runtime allocation)
__device__ float2 g_w1p[25 * 128 * 12];  // conv1 weights: co-pair interleaved, k padded 9->12
__device__ float4 g_w2p[64 * 42];        // pconv weights: k padded 3->4

__device__ __forceinline__ ull pack2(float lo, float hi) {
    ull r; asm("mov.b64 %0, {%1, %2};" : "=l"(r) : "f"(lo), "f"(hi)); return r;
}
__device__ __forceinline__ void unpack2(ull v, float& lo, float& hi) {
    asm("mov.b64 {%0, %1}, %2;" : "=f"(lo), "=f"(hi) : "l"(v));
}
__device__ __forceinline__ void ffma2(ull& d, ull a, ull b) {
    asm("fma.rn.f32x2 %0, %1, %2, %0;" : "+l"(d) : "l"(a), "l"(b));
}

__global__ void prep_kernel(const float* __restrict__ w1, const float* __restrict__ w2) {
    int i = blockIdx.x * blockDim.x + threadIdx.x;
    if (i < 25 * 128 * 12) {
        int k = i % 12;
        int rem = i / 12;
        int ci = rem % 128;
        int cp = rem / 128;
        float lo = 0.f, hi = 0.f;
        if (k < 9) {
            lo = w1[((2 * cp) * 128 + ci) * 9 + k];
            hi = w1[((2 * cp + 1) * 128 + ci) * 9 + k];
        }
        g_w1p[i] = make_float2(lo, hi);
    } else {
        int j = i - 25 * 128 * 12;
        if (j < 64 * 42) {
            const float* s = w2 + j * 3;
            g_w2p[j] = make_float4(s[0], s[1], s[2], 0.f);
        }
    }
}

// Shared memory layout (floats); all float4-touched regions 16B aligned
#define OFF_XT    0        // [128][51], even/odd interleaved rows: 6528
#define OFF_H     6528     // [42][51]: 2142 (pad to 2144)
#define OFF_P     8672     // [64][49]: 3136
#define OFF_U     11808    // [384][8]: 3072
#define OFF_UHAT  14880    // [5*384][16]: 30720
#define OFF_B     45600    // [5][384]: 1920
#define OFF_C     47520    // [5][384]: 1920
#define OFF_SP    49440    // [6][80]: 480
#define OFF_S     49920    // 80
#define OFF_V     50000    // 80
#define OFF_SQ    50080    // 8
#define SMEM_FLTS 50088

__global__ __launch_bounds__(NT, 1)
void caps_kernel(const float* __restrict__ x,
                 const float* __restrict__ b1,
                 const float* __restrict__ b2,
                 const float* __restrict__ W,
                 float* __restrict__ out)
{
    extern __shared__ float sm[];
    float* sXT   = sm + OFF_XT;
    float* sH    = sm + OFF_H;
    float* sP    = sm + OFF_P;
    float* sU    = sm + OFF_U;
    float* sUhat = sm + OFF_UHAT;
    float* sB    = sm + OFF_B;
    float* sC    = sm + OFF_C;
    float* sSp   = sm + OFF_SP;
    float* sS    = sm + OFF_S;
    float* sV    = sm + OFF_V;
    float* sSq   = sm + OFF_SQ;

    const int tid = threadIdx.x;
    const int b   = blockIdx.x;

    // ---- Phase 0: load x[b] -> sXT[ci][interleaved pos] ----
    // x: [B, 50, 128]; sXT row per ci: [0..24]=even pos/2, [26..50]=odd pos/2
    {
        const float* xg = x + (size_t)b * 6400;
        for (int i = tid; i < 6400; i += NT) {
            int pos = i >> 7, ci = i & 127;
            sXT[ci * 51 + (pos >> 1) + 26 * (pos & 1)] = xg[i];
        }
    }
    __syncthreads();

    // ---- Phase 1: conv1 + bias + relu -> sH[l][co] ----
    // y1[co][l] = sum_{ci,k} x[l+k][ci] * w1[co][ci][k]
    if (tid < 525) {
        int cp = tid / 21, lp = tid % 21;  // co pair, l pair
        int l0 = lp << 1, co0 = cp << 1;
        float bb0 = b1[co0], bb1 = b1[co0 + 1];   // hoisted: issue LDGs early
        const ull* wrow = (const ull*)(g_w1p + (size_t)cp * (128 * 12));
        ull acc0 = pack2(0.f, 0.f);  // {y[co0][l0],   y[co0+1][l0]}
        ull acc1 = acc0;             // {y[co0][l0+1], y[co0+1][l0+1]}
        for (int ci = 0; ci < 128; ++ci) {
            const float* xe = sXT + ci * 51 + lp;   // even positions l0, l0+2, ...
            const float* xo = xe + 26;              // odd positions l0+1, l0+3, ...
            float e0 = xe[0], e1 = xe[1], e2 = xe[2], e3 = xe[3], e4 = xe[4];
            float o0 = xo[0], o1 = xo[1], o2 = xo[2], o3 = xo[3], o4 = xo[4];
            ull xd[10];
            xd[0] = pack2(e0, e0); xd[1] = pack2(o0, o0);
            xd[2] = pack2(e1, e1); xd[3] = pack2(o1, o1);
            xd[4] = pack2(e2, e2); xd[5] = pack2(o2, o2);
            xd[6] = pack2(e3, e3); xd[7] = pack2(o3, o3);
            xd[8] = pack2(e4, e4); xd[9] = pack2(o4, o4);
            const ull* wp = wrow + ci * 12;
            #pragma unroll
            for (int k = 0; k < 9; ++k) {
                ull w = wp[k];          // {w1[co0][ci][k], w1[co0+1][ci][k]}
                ffma2(acc0, w, xd[k]);
                ffma2(acc1, w, xd[k + 1]);
            }
        }
        float y00, y10, y01, y11;
        unpack2(acc0, y00, y10);
        unpack2(acc1, y01, y11);
        sH[l0 * 51 + co0]           = fmaxf(y00 + bb0, 0.f);
        sH[l0 * 51 + co0 + 1]       = fmaxf(y10 + bb1, 0.f);
        sH[(l0 + 1) * 51 + co0]     = fmaxf(y01 + bb0, 0.f);
        sH[(l0 + 1) * 51 + co0 + 1] = fmaxf(y11 + bb1, 0.f);
    }
    __syncthreads();

    // ---- Phase 2: pconv -> sP[po][t] ----
    // p[po][t] = sum_{a,k} sH[a][t+k] * w2[po][a][k] + b2[po]
    if (tid < 512) {
        int po = tid >> 3, tg = tid & 7;
        int t0 = tg * 6;
        float bias = b2[po];
        float acc[6] = {0.f, 0.f, 0.f, 0.f, 0.f, 0.f};
        const float4* w2r = g_w2p + po * 42;
        for (int a = 0; a < 42; ++a) {
            float4 w = w2r[a];
            const float* hr = sH + a * 51 + t0;
            float xv[8];
            #pragma unroll
            for (int r = 0; r < 8; ++r) xv[r] = hr[r];
            #pragma unroll
            for (int j = 0; j < 6; ++j)
                acc[j] += w.x * xv[j] + w.y * xv[j + 1] + w.z * xv[j + 2];
        }
        #pragma unroll
        for (int j = 0; j < 6; ++j) sP[po * 49 + t0 + j] = acc[j] + bias;
    }
    __syncthreads();

    // ---- Phase 3: primary-caps squash -> sU[c][i] ----
    // capsule c = po*6 + t/8, i = t%8
    if (tid < 384) {
        int po = tid / 6, g = tid % 6;
        const float* pr = sP + po * 49 + g * 8;
        float q[8];
        float sq = 0.f;
        #pragma unroll
        for (int i = 0; i < 8; ++i) { q[i] = pr[i]; sq += q[i] * q[i]; }
        float scale = (sq / (1.f + sq)) / (sqrtf(sq) + 1e-8f);
        #pragma unroll
        for (int i = 0; i < 8; ++i) sU[tid * 8 + i] = q[i] * scale;
    }
    __syncthreads();

    // ---- Phase 4: u_hat[o][c][d] = sum_i W[o][c][d][i] * u[c][i] ----
    for (int p = tid; p < 1920; p += NT) {
        int c = p % 384;
        float4 u0 = *(const float4*)(sU + c * 8);
        float4 u1 = *(const float4*)(sU + c * 8 + 4);
        const float4* wp = (const float4*)(W + (size_t)p * 128);
        float* uh = sUhat + p * 16;
        #pragma unroll
        for (int d = 0; d < 16; ++d) {
            float4 wa = __ldg(wp + 2 * d);
            float4 wb = __ldg(wp + 2 * d + 1);
            uh[d] = wa.x * u0.x + wa.y * u0.y + wa.z * u0.z + wa.w * u0.w
                  + wb.x * u1.x + wb.y * u1.y + wb.z * u1.z + wb.w * u1.w;
        }
    }
    for (int i = tid; i < 1920; i += NT) sB[i] = 0.f;
    __syncthreads();

    // ---- Phase 5: dynamic routing (3 iterations) ----
    for (int it = 0; it < 3; ++it) {
        // c = softmax over o (axis of size 5), per capsule c
        if (tid < 384) {
            float bb[5], m = -1e30f;
            #pragma unroll
            for (int o = 0; o < 5; ++o) { bb[o] = sB[o * 384 + tid]; m = fmaxf(m, bb[o]); }
            float e[5], ssum = 0.f;
            #pragma unroll
            for (int o = 0; o < 5; ++o) { e[o] = expf(bb[o] - m); ssum += e[o]; }
            float inv = 1.f / ssum;
            #pragma unroll
            for (int o = 0; o < 5; ++o) sC[o * 384 + tid] = e[o] * inv;
        }
        __syncthreads();
        // s[o][d] = sum_c c[o][c] * u_hat[o][c][d]  (6-way split over c)
        if (tid < 480) {
            int od = tid % 80, ch = tid / 80;
            int o = od >> 4, d = od & 15;
            const float* uh = sUhat + o * 384 * 16 + d;
            const float* cc = sC + o * 384;
            float acc = 0.f;
            int c0 = ch * 64;
            for (int c = c0; c < c0 + 64; ++c) acc += cc[c] * uh[c * 16];
            sSp[ch * 80 + od] = acc;
        }
        __syncthreads();
        if (tid < 80) {
            float s = 0.f;
            #pragma unroll
            for (int ch = 0; ch < 6; ++ch) s += sSp[ch * 80 + tid];
            sS[tid] = s;
        }
        __syncthreads();
        if (tid < 5) {
            float sq = 0.f;
            #pragma unroll
            for (int d = 0; d < 16; ++d) { float v = sS[tid * 16 + d]; sq += v * v; }
            sSq[tid] = sq;
        }
        __syncthreads();
        if (tid < 80) {
            int o = tid >> 4;
            float sq = sSq[o];
            float v = sS[tid] * (sq / (1.f + sq)) / (sqrtf(sq) + 1e-8f);
            sV[tid] = v;
            if (it == 2) out[(size_t)b * 80 + tid] = v;
        }
        __syncthreads();
        if (it < 2) {
            // b[o][c] += sum_d u_hat[o][c][d] * v[o][d]
            for (int p = tid; p < 1920; p += NT) {
                int o = p / 384;
                const float4* uh = (const float4*)(sUhat + p * 16);
                const float4* vv = (const float4*)(sV + o * 16);
                float acc = 0.f;
                #pragma unroll
                for (int q = 0; q < 4; ++q) {
                    float4 a = uh[q], w = vv[q];
                    acc += a.x * w.x + a.y * w.y + a.z * w.z + a.w * w.w;
                }
                sB[p] += acc;
            }
            __syncthreads();
        }
    }
}

extern "C" void kernel_launch(void* const* d_in, const int* in_sizes, int n_in,
                              void* d_out, int out_size) {
    const float* x  = (const float*)d_in[0];
    const float* w1 = (const float*)d_in[1];
    const float* b1 = (const float*)d_in[2];
    const float* w2 = (const float*)d_in[3];
    const float* b2 = (const float*)d_in[4];
    const float* W  = (const float*)d_in[5];
    float* out = (float*)d_out;

    int B = in_sizes[0] / 6400;

    size_t smem_bytes = SMEM_FLTS * sizeof(float);
    cudaFuncSetAttribute(caps_kernel, cudaFuncAttributeMaxDynamicSharedMemorySize,
                         (int)smem_bytes);

    int prep_n = 25 * 128 * 12 + 64 * 42;
    prep_kernel<<<(prep_n + 255) / 256, 256>>>(w1, w2);
    caps_kernel<<<B, NT, smem_bytes>>>(x, b1, b2, W, out);
}

// round 7
// speedup vs baseline: 1.1812x; 1.1812x over previous
#include <cuda_runtime.h>

#define NT 544

typedef unsigned long long ull;

// Scratch (allowed: __device__ globals, no runtime allocation)
__device__ float2 g_w1p[25 * 128 * 12];  // conv1 weights: co-pair interleaved, k padded 9->12
__device__ float4 g_w2p[64 * 42];        // pconv weights: k padded 3->4

__device__ __forceinline__ ull pack2(float lo, float hi) {
    ull r; asm("mov.b64 %0, {%1, %2};" : "=l"(r) : "f"(lo), "f"(hi)); return r;
}
__device__ __forceinline__ void unpack2(ull v, float& lo, float& hi) {
    asm("mov.b64 {%0, %1}, %2;" : "=f"(lo), "=f"(hi) : "l"(v));
}
__device__ __forceinline__ void ffma2(ull& d, ull a, ull b) {
    asm("fma.rn.f32x2 %0, %1, %2, %0;" : "+l"(d) : "l"(a), "l"(b));
}

__global__ void prep_kernel(const float* __restrict__ w1, const float* __restrict__ w2) {
    int i = blockIdx.x * blockDim.x + threadIdx.x;
    if (i < 25 * 128 * 12) {
        int k = i % 12;
        int rem = i / 12;
        int ci = rem % 128;
        int cp = rem / 128;
        float lo = 0.f, hi = 0.f;
        if (k < 9) {
            lo = w1[((2 * cp) * 128 + ci) * 9 + k];
            hi = w1[((2 * cp + 1) * 128 + ci) * 9 + k];
        }
        g_w1p[i] = make_float2(lo, hi);
    } else {
        int j = i - 25 * 128 * 12;
        if (j < 64 * 42) {
            const float* s = w2 + j * 3;
            g_w2p[j] = make_float4(s[0], s[1], s[2], 0.f);
        }
    }
}

// Shared memory layout (floats)
#define OFF_XT    0        // [128][52] stride-1 positions, cols 50/51 zero pad: 6656
#define OFF_H     6656     // [42][51]: 2142 pad 2144
#define OFF_P     8800     // [64][49]: 3136
#define OFF_U     11936    // [384][8]: 3072 (16B aligned: 11936%4==0)
#define OFF_UHAT  15008    // [1920][17] padded stride: 32640
#define OFF_B     47648    // [5][384]: 1920
#define OFF_C     49568    // [5][384]: 1920
#define OFF_SP    51488    // [6][80]: 480
#define OFF_S     51968    // 80
#define OFF_V     52048    // 80
#define OFF_SQ    52128    // 8
#define SMEM_FLTS 52136

#define UH_STRIDE 17

__global__ __launch_bounds__(NT, 1)
void caps_kernel(const float* __restrict__ x,
                 const float* __restrict__ b1,
                 const float* __restrict__ b2,
                 const float* __restrict__ W,
                 float* __restrict__ out)
{
    extern __shared__ float sm[];
    float* sXT   = sm + OFF_XT;
    float* sH    = sm + OFF_H;
    float* sP    = sm + OFF_P;
    float* sU    = sm + OFF_U;
    float* sUhat = sm + OFF_UHAT;
    float* sB    = sm + OFF_B;
    float* sC    = sm + OFF_C;
    float* sSp   = sm + OFF_SP;
    float* sS    = sm + OFF_S;
    float* sV    = sm + OFF_V;
    float* sSq   = sm + OFF_SQ;

    const int tid = threadIdx.x;
    const int b   = blockIdx.x;

    // ---- Phase 0: load x[b] -> sXT[ci][pos], stride-1 positions ----
    {
        const float* xg = x + (size_t)b * 6400;
        for (int i = tid; i < 6400; i += NT) {
            int pos = i >> 7, ci = i & 127;
            sXT[ci * 52 + pos] = xg[i];
        }
        // zero pad columns 50,51 (read by the l0=40 tile, results discarded)
        if (tid < 256) {
            int ci = tid >> 1;
            sXT[ci * 52 + 50 + (tid & 1)] = 0.f;
        }
    }
    __syncthreads();

    // ---- Phase 1: conv1 + bias + relu -> sH[l][co] ----
    // 2co x 4l tile per thread: 25 co-pairs x 11 l-groups = 275 threads
    if (tid < 275) {
        int cp = tid / 11, j = tid % 11;
        int l0 = j << 2, co0 = cp << 1;
        float bb0 = b1[co0], bb1 = b1[co0 + 1];
        const ull* wrow = (const ull*)g_w1p + (size_t)cp * (128 * 12);
        ull acc0 = pack2(0.f, 0.f);
        ull acc1 = acc0, acc2 = acc0, acc3 = acc0;
        for (int ci = 0; ci < 128; ++ci) {
            const float4* xr = (const float4*)(sXT + ci * 52 + l0);
            float4 xa = xr[0], xb = xr[1], xc = xr[2];   // x[l0 .. l0+11]
            ull xd[12];
            xd[0]  = pack2(xa.x, xa.x); xd[1]  = pack2(xa.y, xa.y);
            xd[2]  = pack2(xa.z, xa.z); xd[3]  = pack2(xa.w, xa.w);
            xd[4]  = pack2(xb.x, xb.x); xd[5]  = pack2(xb.y, xb.y);
            xd[6]  = pack2(xb.z, xb.z); xd[7]  = pack2(xb.w, xb.w);
            xd[8]  = pack2(xc.x, xc.x); xd[9]  = pack2(xc.y, xc.y);
            xd[10] = pack2(xc.z, xc.z); xd[11] = pack2(xc.w, xc.w);
            const ull* wp = wrow + ci * 12;
            #pragma unroll
            for (int k = 0; k < 9; ++k) {
                ull w = wp[k];   // {w1[co0][ci][k], w1[co0+1][ci][k]}
                ffma2(acc0, w, xd[k]);
                ffma2(acc1, w, xd[k + 1]);
                ffma2(acc2, w, xd[k + 2]);
                ffma2(acc3, w, xd[k + 3]);
            }
        }
        float y0a, y0b, y1a, y1b, y2a, y2b, y3a, y3b;
        unpack2(acc0, y0a, y0b);
        unpack2(acc1, y1a, y1b);
        unpack2(acc2, y2a, y2b);
        unpack2(acc3, y3a, y3b);
        float ya[4] = {y0a, y1a, y2a, y3a};
        float yb[4] = {y0b, y1b, y2b, y3b};
        #pragma unroll
        for (int m = 0; m < 4; ++m) {
            int l = l0 + m;
            if (l < 42) {
                sH[l * 51 + co0]     = fmaxf(ya[m] + bb0, 0.f);
                sH[l * 51 + co0 + 1] = fmaxf(yb[m] + bb1, 0.f);
            }
        }
    }
    __syncthreads();

    // ---- Phase 2: pconv -> sP[po][t] ----
    if (tid < 512) {
        int po = tid >> 3, tg = tid & 7;
        int t0 = tg * 6;
        float bias = b2[po];
        float acc[6] = {0.f, 0.f, 0.f, 0.f, 0.f, 0.f};
        const float4* w2r = g_w2p + po * 42;
        for (int a = 0; a < 42; ++a) {
            float4 w = w2r[a];
            const float* hr = sH + a * 51 + t0;
            float xv[8];
            #pragma unroll
            for (int r = 0; r < 8; ++r) xv[r] = hr[r];
            #pragma unroll
            for (int j = 0; j < 6; ++j)
                acc[j] += w.x * xv[j] + w.y * xv[j + 1] + w.z * xv[j + 2];
        }
        #pragma unroll
        for (int j = 0; j < 6; ++j) sP[po * 49 + t0 + j] = acc[j] + bias;
    }
    __syncthreads();

    // ---- Phase 3: primary-caps squash -> sU[c][i] ----
    if (tid < 384) {
        int po = tid / 6, g = tid % 6;
        const float* pr = sP + po * 49 + g * 8;
        float q[8];
        float sq = 0.f;
        #pragma unroll
        for (int i = 0; i < 8; ++i) { q[i] = pr[i]; sq += q[i] * q[i]; }
        float scale = (sq / (1.f + sq)) / (sqrtf(sq) + 1e-8f);
        #pragma unroll
        for (int i = 0; i < 8; ++i) sU[tid * 8 + i] = q[i] * scale;
    }
    __syncthreads();

    // ---- Phase 4: u_hat[o][c][d] = sum_i W[o][c][d][i] * u[c][i] ----
    for (int p = tid; p < 1920; p += NT) {
        int c = p % 384;
        float4 u0 = *(const float4*)(sU + c * 8);
        float4 u1 = *(const float4*)(sU + c * 8 + 4);
        const float4* wp = (const float4*)(W + (size_t)p * 128);
        float* uh = sUhat + p * UH_STRIDE;
        #pragma unroll
        for (int d = 0; d < 16; ++d) {
            float4 wa = __ldg(wp + 2 * d);
            float4 wb = __ldg(wp + 2 * d + 1);
            uh[d] = wa.x * u0.x + wa.y * u0.y + wa.z * u0.z + wa.w * u0.w
                  + wb.x * u1.x + wb.y * u1.y + wb.z * u1.z + wb.w * u1.w;
        }
    }
    for (int i = tid; i < 1920; i += NT) sB[i] = 0.f;
    __syncthreads();

    // ---- Phase 5: dynamic routing (3 iterations) ----
    for (int it = 0; it < 3; ++it) {
        // c = softmax over o (axis of size 5), per capsule c
        if (tid < 384) {
            float bb[5], m = -1e30f;
            #pragma unroll
            for (int o = 0; o < 5; ++o) { bb[o] = sB[o * 384 + tid]; m = fmaxf(m, bb[o]); }
            float e[5], ssum = 0.f;
            #pragma unroll
            for (int o = 0; o < 5; ++o) { e[o] = expf(bb[o] - m); ssum += e[o]; }
            float inv = 1.f / ssum;
            #pragma unroll
            for (int o = 0; o < 5; ++o) sC[o * 384 + tid] = e[o] * inv;
        }
        __syncthreads();
        // s[o][d] = sum_c c[o][c] * u_hat[o][c][d]  (6-way split over c)
        if (tid < 480) {
            int od = tid % 80, ch = tid / 80;
            int o = od >> 4, d = od & 15;
            const float* uh = sUhat + (size_t)o * 384 * UH_STRIDE + d;
            const float* cc = sC + o * 384;
            float acc = 0.f;
            int c0 = ch * 64;
            for (int c = c0; c < c0 + 64; ++c) acc += cc[c] * uh[c * UH_STRIDE];
            sSp[ch * 80 + od] = acc;
        }
        __syncthreads();
        if (tid < 80) {
            float s = 0.f;
            #pragma unroll
            for (int ch = 0; ch < 6; ++ch) s += sSp[ch * 80 + tid];
            sS[tid] = s;
        }
        __syncthreads();
        if (tid < 5) {
            float sq = 0.f;
            #pragma unroll
            for (int d = 0; d < 16; ++d) { float v = sS[tid * 16 + d]; sq += v * v; }
            sSq[tid] = sq;
        }
        __syncthreads();
        if (tid < 80) {
            int o = tid >> 4;
            float sq = sSq[o];
            float v = sS[tid] * (sq / (1.f + sq)) / (sqrtf(sq) + 1e-8f);
            sV[tid] = v;
            if (it == 2) out[(size_t)b * 80 + tid] = v;
        }
        __syncthreads();
        if (it < 2) {
            // b[o][c] += sum_d u_hat[o][c][d] * v[o][d]  (scalar, conflict-free)
            for (int p = tid; p < 1920; p += NT) {
                int o = p / 384;
                const float* uh = sUhat + p * UH_STRIDE;
                const float* vv = sV + o * 16;
                float acc = 0.f;
                #pragma unroll
                for (int q = 0; q < 16; ++q) acc += uh[q] * vv[q];
                sB[p] += acc;
            }
            __syncthreads();
        }
    }
}

extern "C" void kernel_launch(void* const* d_in, const int* in_sizes, int n_in,
                              void* d_out, int out_size) {
    const float* x  = (const float*)d_in[0];
    const float* w1 = (const float*)d_in[1];
    const float* b1 = (const float*)d_in[2];
    const float* w2 = (const float*)d_in[3];
    const float* b2 = (const float*)d_in[4];
    const float* W  = (const float*)d_in[5];
    float* out = (float*)d_out;

    int B = in_sizes[0] / 6400;

    size_t smem_bytes = SMEM_FLTS * sizeof(float);
    cudaFuncSetAttribute(caps_kernel, cudaFuncAttributeMaxDynamicSharedMemorySize,
                         (int)smem_bytes);

    int prep_n = 25 * 128 * 12 + 64 * 42;
    prep_kernel<<<(prep_n + 255) / 256, 256>>>(w1, w2);
    caps_kernel<<<B, NT, smem_bytes>>>(x, b1, b2, W, out);
}

// round 8
// speedup vs baseline: 2.0719x; 1.7540x over previous
#include <cuda_runtime.h>

#define NT 544

typedef unsigned long long ull;

// Scratch (allowed: __device__ globals, no runtime allocation)
__device__ float2 g_w1q[25 * 128 * 9];   // (cp, ci, k): {w[2cp], w[2cp+1]}, contiguous k-stride 9
__device__ float4 g_w2p[64 * 42];        // pconv weights: k padded 3->4
__device__ float2 g_Wt2[128 * 960];      // [(d*8+i)*960 + pair] = {W[p0][d][i], W[p0+1][d][i]}, p0=2*pair

#define W1Q_N (25 * 128 * 9)
#define W2P_N (64 * 42)
#define WT2_N (128 * 960)

__device__ __forceinline__ ull pack2(float lo, float hi) {
    ull r; asm("mov.b64 %0, {%1, %2};" : "=l"(r) : "f"(lo), "f"(hi)); return r;
}
__device__ __forceinline__ void unpack2(ull v, float& lo, float& hi) {
    asm("mov.b64 {%0, %1}, %2;" : "=f"(lo), "=f"(hi) : "l"(v));
}
__device__ __forceinline__ void ffma2(ull& d, ull a, ull b) {
    asm("fma.rn.f32x2 %0, %1, %2, %0;" : "+l"(d) : "l"(a), "l"(b));
}

__global__ void prep_kernel(const float* __restrict__ w1, const float* __restrict__ w2,
                            const float* __restrict__ W) {
    int idx = blockIdx.x * blockDim.x + threadIdx.x;
    if (idx < W1Q_N) {
        int k = idx % 9;
        int rem = idx / 9;
        int ci = rem % 128;
        int cp = rem / 128;
        float lo = w1[((2 * cp) * 128 + ci) * 9 + k];
        float hi = w1[((2 * cp + 1) * 128 + ci) * 9 + k];
        g_w1q[idx] = make_float2(lo, hi);
    } else if (idx < W1Q_N + W2P_N) {
        int j = idx - W1Q_N;
        const float* s = w2 + j * 3;
        g_w2p[j] = make_float4(s[0], s[1], s[2], 0.f);
    } else {
        int t = idx - (W1Q_N + W2P_N);
        if (t < WT2_N) {
            int pair = t % 960;
            int di = t / 960;          // d*8 + i
            int p0 = 2 * pair;
            int o = p0 / 384, c0 = p0 % 384;
            // W layout [5,384,16,8]: o*49152 + c*128 + di
            float lo = W[(size_t)o * 49152 + c0 * 128 + di];
            float hi = W[(size_t)o * 49152 + (c0 + 1) * 128 + di];
            g_Wt2[t] = make_float2(lo, hi);
        }
    }
}

// Shared memory layout (floats)
#define OFF_XT    0        // [128][52] stride-1 positions, cols 50/51 zero pad: 6656
#define OFF_H     6656     // [42][51]: 2142 pad 2144
#define OFF_P     8800     // [64][49]: 3136
#define OFF_U     11936    // [384][8]: 3072 (16B aligned)
#define OFF_UHAT  15008    // 5 * 6536 = 32680 (o-stride padded); also aliased as weight stage
#define OFF_B     47688    // [5][384]: 1920
#define OFF_C     49608    // [5][384]: 1920
#define OFF_SP    51528    // [6][80]: 480
#define OFF_S     52008    // 80
#define OFF_V     52088    // 80
#define OFF_SQ    52168    // 8
#define SMEM_FLTS 52176

#define UH_STRIDE 17
#define O_STRIDE  6536     // 384*17 + 8 pad: o-groups land in distinct banks
#define W1_CP_STRIDE 289   // ull stride per cp in staged conv1 weights (32*9 + 1 pad)

__global__ __launch_bounds__(NT, 1)
void caps_kernel(const float* __restrict__ x,
                 const float* __restrict__ b1,
                 const float* __restrict__ b2,
                 float* __restrict__ out)
{
    extern __shared__ float sm[];
    float* sXT   = sm + OFF_XT;
    float* sH    = sm + OFF_H;
    float* sP    = sm + OFF_P;
    float* sU    = sm + OFF_U;
    float* sUhat = sm + OFF_UHAT;
    float* sB    = sm + OFF_B;
    float* sC    = sm + OFF_C;
    float* sSp   = sm + OFF_SP;
    float* sS    = sm + OFF_S;
    float* sV    = sm + OFF_V;
    float* sSq   = sm + OFF_SQ;

    const int tid = threadIdx.x;
    const int b   = blockIdx.x;

    // ---- Phase 0: load x[b] -> sXT[ci][pos] ----
    {
        const float* xg = x + (size_t)b * 6400;
        for (int i = tid; i < 6400; i += NT) {
            int pos = i >> 7, ci = i & 127;
            sXT[ci * 52 + pos] = xg[i];
        }
        if (tid < 256) {
            int ci = tid >> 1;
            sXT[ci * 52 + 50 + (tid & 1)] = 0.f;
        }
    }
    __syncthreads();

    // ---- Phase 1: conv1 + bias + relu -> sH[l][co], weights staged per ci-chunk ----
    // 2co x 4l tile per thread: 25 co-pairs x 11 l-groups = 275 threads
    {
        ull* sW = (ull*)(sm + OFF_UHAT);   // 25 * 289 ull = 57.8KB, 8B-aligned
        int cp = 0, l0 = 0;
        float bb0 = 0.f, bb1 = 0.f;
        ull acc0 = pack2(0.f, 0.f);
        ull acc1 = acc0, acc2 = acc0, acc3 = acc0;
        if (tid < 275) {
            cp = tid / 11;
            l0 = (tid % 11) << 2;
            bb0 = b1[2 * cp]; bb1 = b1[2 * cp + 1];
        }
        const float2* w1q = g_w1q;
        for (int chunk = 0; chunk < 4; ++chunk) {
            int c0 = chunk << 5;
            // stage: sW[cp][ci_local*9 + k], padded cp stride
            for (int i = tid; i < 7200; i += NT) {
                int cpi = i / 288, rest = i - cpi * 288;
                float2 v = w1q[cpi * 1152 + c0 * 9 + rest];
                sW[cpi * W1_CP_STRIDE + rest] = *(const ull*)&v;
            }
            __syncthreads();
            if (tid < 275) {
                const ull* wrow = sW + cp * W1_CP_STRIDE;
                for (int cl = 0; cl < 32; ++cl) {
                    int ci = c0 + cl;
                    const float4* xr = (const float4*)(sXT + ci * 52 + l0);
                    float4 xa = xr[0], xb = xr[1], xc = xr[2];
                    ull xd[12];
                    xd[0]  = pack2(xa.x, xa.x); xd[1]  = pack2(xa.y, xa.y);
                    xd[2]  = pack2(xa.z, xa.z); xd[3]  = pack2(xa.w, xa.w);
                    xd[4]  = pack2(xb.x, xb.x); xd[5]  = pack2(xb.y, xb.y);
                    xd[6]  = pack2(xb.z, xb.z); xd[7]  = pack2(xb.w, xb.w);
                    xd[8]  = pack2(xc.x, xc.x); xd[9]  = pack2(xc.y, xc.y);
                    xd[10] = pack2(xc.z, xc.z); xd[11] = pack2(xc.w, xc.w);
                    const ull* wp = wrow + cl * 9;
                    #pragma unroll
                    for (int k = 0; k < 9; ++k) {
                        ull w = wp[k];
                        ffma2(acc0, w, xd[k]);
                        ffma2(acc1, w, xd[k + 1]);
                        ffma2(acc2, w, xd[k + 2]);
                        ffma2(acc3, w, xd[k + 3]);
                    }
                }
            }
            __syncthreads();
        }
        if (tid < 275) {
            int co0 = cp << 1;
            float y0a, y0b, y1a, y1b, y2a, y2b, y3a, y3b;
            unpack2(acc0, y0a, y0b);
            unpack2(acc1, y1a, y1b);
            unpack2(acc2, y2a, y2b);
            unpack2(acc3, y3a, y3b);
            float ya[4] = {y0a, y1a, y2a, y3a};
            float yb[4] = {y0b, y1b, y2b, y3b};
            #pragma unroll
            for (int m = 0; m < 4; ++m) {
                int l = l0 + m;
                if (l < 42) {
                    sH[l * 51 + co0]     = fmaxf(ya[m] + bb0, 0.f);
                    sH[l * 51 + co0 + 1] = fmaxf(yb[m] + bb1, 0.f);
                }
            }
        }
    }
    __syncthreads();

    // ---- Phase 2: pconv -> sP[po][t], weights staged in smem ----
    {
        float4* sW2 = (float4*)(sm + OFF_UHAT);   // 2688 float4 = 43KB
        for (int i = tid; i < 2688; i += NT) sW2[i] = g_w2p[i];
        __syncthreads();
        if (tid < 512) {
            int po = tid >> 3, tg = tid & 7;
            int t0 = tg * 6;
            float bias = b2[po];
            float acc[6] = {0.f, 0.f, 0.f, 0.f, 0.f, 0.f};
            const float4* w2r = sW2 + po * 42;
            for (int a = 0; a < 42; ++a) {
                float4 w = w2r[a];
                const float* hr = sH + a * 51 + t0;
                float xv[8];
                #pragma unroll
                for (int r = 0; r < 8; ++r) xv[r] = hr[r];
                #pragma unroll
                for (int j = 0; j < 6; ++j)
                    acc[j] += w.x * xv[j] + w.y * xv[j + 1] + w.z * xv[j + 2];
            }
            #pragma unroll
            for (int j = 0; j < 6; ++j) sP[po * 49 + t0 + j] = acc[j] + bias;
        }
    }
    __syncthreads();

    // ---- Phase 3: primary-caps squash -> sU[c][i] ----
    if (tid < 384) {
        int po = tid / 6, g = tid % 6;
        const float* pr = sP + po * 49 + g * 8;
        float q[8];
        float sq = 0.f;
        #pragma unroll
        for (int i = 0; i < 8; ++i) { q[i] = pr[i]; sq += q[i] * q[i]; }
        float scale = (sq / (1.f + sq)) / (sqrtf(sq) + 1e-8f);
        #pragma unroll
        for (int i = 0; i < 8; ++i) sU[tid * 8 + i] = q[i] * scale;
    }
    __syncthreads();

    // ---- Phase 4: u_hat via transposed W (coalesced), 2 capsule-pairs per thread ----
    {
        const ull* Wt = (const ull*)g_Wt2;
        for (int pair = tid; pair < 960; pair += NT) {
            int o = pair / 192;              // p0 = 2*pair, o = p0/384
            int c0 = 2 * pair - o * 384;
            const float4* ua = (const float4*)(sU + c0 * 8);
            float4 A0 = ua[0], A1 = ua[1];   // u[c0]
            float4 B0 = ua[2], B1 = ua[3];   // u[c0+1]
            ull uu[8];
            uu[0] = pack2(A0.x, B0.x); uu[1] = pack2(A0.y, B0.y);
            uu[2] = pack2(A0.z, B0.z); uu[3] = pack2(A0.w, B0.w);
            uu[4] = pack2(A1.x, B1.x); uu[5] = pack2(A1.y, B1.y);
            uu[6] = pack2(A1.z, B1.z); uu[7] = pack2(A1.w, B1.w);
            float* uh0 = sUhat + o * O_STRIDE + c0 * UH_STRIDE;
            float* uh1 = uh0 + UH_STRIDE;
            const ull* wp = Wt + pair;
            #pragma unroll
            for (int d = 0; d < 16; ++d) {
                ull acc = pack2(0.f, 0.f);
                #pragma unroll
                for (int i = 0; i < 8; ++i)
                    ffma2(acc, wp[(d * 8 + i) * 960], uu[i]);
                float r0, r1;
                unpack2(acc, r0, r1);
                uh0[d] = r0;
                uh1[d] = r1;
            }
        }
    }
    for (int i = tid; i < 1920; i += NT) sB[i] = 0.f;
    __syncthreads();

    // ---- Phase 5: dynamic routing (3 iterations) ----
    for (int it = 0; it < 3; ++it) {
        // c = softmax over o (axis of size 5), per capsule c
        if (tid < 384) {
            float bb[5], m = -1e30f;
            #pragma unroll
            for (int o = 0; o < 5; ++o) { bb[o] = sB[o * 384 + tid]; m = fmaxf(m, bb[o]); }
            float e[5], ssum = 0.f;
            #pragma unroll
            for (int o = 0; o < 5; ++o) { e[o] = expf(bb[o] - m); ssum += e[o]; }
            float inv = 1.f / ssum;
            #pragma unroll
            for (int o = 0; o < 5; ++o) sC[o * 384 + tid] = e[o] * inv;
        }
        __syncthreads();
        // s[o][d] = sum_c c[o][c] * u_hat[o][c][d]  (6-way split over c)
        if (tid < 480) {
            int od = tid % 80, ch = tid / 80;
            int o = od >> 4, d = od & 15;
            const float* uh = sUhat + o * O_STRIDE + d;
            const float* cc = sC + o * 384;
            float acc = 0.f;
            int c0 = ch * 64;
            for (int c = c0; c < c0 + 64; ++c) acc += cc[c] * uh[c * UH_STRIDE];
            sSp[ch * 80 + od] = acc;
        }
        __syncthreads();
        if (tid < 80) {
            float s = 0.f;
            #pragma unroll
            for (int ch = 0; ch < 6; ++ch) s += sSp[ch * 80 + tid];
            sS[tid] = s;
        }
        __syncthreads();
        if (tid < 5) {
            float sq = 0.f;
            #pragma unroll
            for (int d = 0; d < 16; ++d) { float v = sS[tid * 16 + d]; sq += v * v; }
            sSq[tid] = sq;
        }
        __syncthreads();
        if (tid < 80) {
            int o = tid >> 4;
            float sq = sSq[o];
            float v = sS[tid] * (sq / (1.f + sq)) / (sqrtf(sq) + 1e-8f);
            sV[tid] = v;
            if (it == 2) out[(size_t)b * 80 + tid] = v;
        }
        __syncthreads();
        if (it < 2) {
            // b[o][c] += sum_d u_hat[o][c][d] * v[o][d]  (scalar, conflict-free)
            for (int p = tid; p < 1920; p += NT) {
                int o = p / 384;
                int c = p - o * 384;
                const float* uh = sUhat + o * O_STRIDE + c * UH_STRIDE;
                const float* vv = sV + o * 16;
                float acc = 0.f;
                #pragma unroll
                for (int q = 0; q < 16; ++q) acc += uh[q] * vv[q];
                sB[p] += acc;
            }
            __syncthreads();
        }
    }
}

extern "C" void kernel_launch(void* const* d_in, const int* in_sizes, int n_in,
                              void* d_out, int out_size) {
    const float* x  = (const float*)d_in[0];
    const float* w1 = (const float*)d_in[1];
    const float* b1 = (const float*)d_in[2];
    const float* w2 = (const float*)d_in[3];
    const float* b2 = (const float*)d_in[4];
    const float* W  = (const float*)d_in[5];
    float* out = (float*)d_out;

    int B = in_sizes[0] / 6400;

    size_t smem_bytes = SMEM_FLTS * sizeof(float);
    cudaFuncSetAttribute(caps_kernel, cudaFuncAttributeMaxDynamicSharedMemorySize,
                         (int)smem_bytes);

    int prep_n = W1Q_N + W2P_N + WT2_N;
    prep_kernel<<<(prep_n + 255) / 256, 256>>>(w1, w2, W);
    caps_kernel<<<B, NT, smem_bytes>>>(x, b1, b2, out);
}